// round 1
// baseline (speedup 1.0000x reference)
#include <cuda_runtime.h>
#include <cstdint>

#define BB 32
#define TT 2048
#define DD 512
#define UU 512

// Scratch (no device allocation allowed)
__device__ float g_projh[BB * UU];
__device__ float g_logits[BB * TT];

// ---------------------------------------------------------------------------
// helpers
// ---------------------------------------------------------------------------
__device__ __forceinline__ uint32_t f2tf32(float x) {
    uint32_t r;
    asm("cvt.rna.tf32.f32 %0, %1;" : "=r"(r) : "f"(x));
    return r;
}

__device__ __forceinline__ float fast_tanh(float x) {
    // tanh(x) = 1 - 2/(e^{2x}+1); exact at +-inf limits, err ~1e-6
    float e = __expf(2.0f * x);
    return 1.0f - __fdividef(2.0f, e + 1.0f);
}

__device__ __forceinline__ void cp16(float* s, const float* g) {
    uint32_t sa = (uint32_t)__cvta_generic_to_shared(s);
    asm volatile("cp.async.cg.shared.global [%0], [%1], 16;" ::"r"(sa), "l"(g) : "memory");
}

__device__ __forceinline__ void mma_tf32(float* c, const uint32_t* a, uint32_t b0, uint32_t b1) {
    asm volatile(
        "mma.sync.aligned.m16n8k8.row.col.f32.tf32.tf32.f32 "
        "{%0,%1,%2,%3}, {%4,%5,%6,%7}, {%8,%9}, {%0,%1,%2,%3};"
        : "+f"(c[0]), "+f"(c[1]), "+f"(c[2]), "+f"(c[3])
        : "r"(a[0]), "r"(a[1]), "r"(a[2]), "r"(a[3]), "r"(b0), "r"(b1));
}

// ---------------------------------------------------------------------------
// K0: proj_h[b,u] = hidden[b,:] . W2[:,u] + b2[u]
// ---------------------------------------------------------------------------
__global__ void projh_kernel(const float* __restrict__ hidden,
                             const float* __restrict__ W2,
                             const float* __restrict__ b2) {
    __shared__ float hs[DD];
    int b = blockIdx.x, u = threadIdx.x;  // 512 threads
    hs[u] = hidden[b * DD + u];
    __syncthreads();
    float acc = b2[u];
#pragma unroll 16
    for (int d = 0; d < DD; d++) acc = fmaf(hs[d], W2[d * UU + u], acc);
    g_projh[b * UU + u] = acc;
}

// ---------------------------------------------------------------------------
// K1: fused  logits[m] = sum_u tanh(feat[m,:].W1[:,u] + b1[u] + projh[b,u]) * V[u] + bv
// CTA: 128 rows (m) x full U, tf32 mma.sync, N processed in 4 chunks of 128.
// smem (floats): As[2][128*44]=11264 | Bs[2][32*132]=8448 | projh[128] | Vs[128] | logit[128]
// ---------------------------------------------------------------------------
#define A_LD 44
#define B_LD 132
#define A_STAGE (128 * A_LD)         // 5632
#define BS_BASE (2 * A_STAGE)        // 11264
#define B_STAGE (32 * B_LD)          // 4224
#define PROJH_OFF (BS_BASE + 2 * B_STAGE)   // 19712
#define VS_OFF (PROJH_OFF + 128)            // 19840
#define LOGIT_OFF (VS_OFF + 128)            // 19968
#define SMEM_FLOATS (LOGIT_OFF + 128)       // 20096
#define SMEM_BYTES (SMEM_FLOATS * 4)        // 80384

__global__ void __launch_bounds__(256, 2)
fused_score_kernel(const float* __restrict__ features, const float* __restrict__ W1,
                   const float* __restrict__ b1, const float* __restrict__ V,
                   const float* __restrict__ bv) {
    extern __shared__ float sm[];
    const int tid = threadIdx.x;
    const int warp = tid >> 5, lane = tid & 31;
    const int wm = warp & 3, wn = warp >> 2;
    const int g = lane >> 2, tg = lane & 3;
    const int mbase = wm * 32, nbase = wn * 64;
    const int m0 = blockIdx.x * 128;
    const int bb = m0 >> 11;  // batch index (T=2048)

    float* projh_s = sm + PROJH_OFF;
    float* Vs      = sm + VS_OFF;
    float* logit_s = sm + LOGIT_OFF;

    if (tid < 128) logit_s[tid] = 0.f;

    for (int nc = 0; nc < 4; nc++) {
        __syncthreads();  // protects projh_s/Vs rewrite vs previous epilogue
        if (tid < 128) {
            int u = nc * 128 + tid;
            projh_s[tid] = g_projh[bb * UU + u] + b1[u];
            Vs[tid] = V[u];
        }

        float c[2][8][4];
#pragma unroll
        for (int i = 0; i < 2; i++)
#pragma unroll
            for (int j = 0; j < 8; j++)
#pragma unroll
                for (int k = 0; k < 4; k++) c[i][j][k] = 0.f;

        // prologue: load k-chunk 0 into stage 0
        {
            float* As = sm;
            float* Bs = sm + BS_BASE;
            const float* Ag = features + (size_t)m0 * DD;
#pragma unroll
            for (int j = 0; j < 4; j++) {
                int idx = tid + j * 256;
                int r = idx >> 3, c4 = idx & 7;
                cp16(As + r * A_LD + c4 * 4, Ag + (size_t)r * DD + c4 * 4);
            }
            const float* Bg = W1 + nc * 128;
#pragma unroll
            for (int j = 0; j < 4; j++) {
                int idx = tid + j * 256;
                int r = idx >> 5, c4 = idx & 31;
                cp16(Bs + r * B_LD + c4 * 4, Bg + (size_t)r * UU + c4 * 4);
            }
            asm volatile("cp.async.commit_group;" ::: "memory");
        }

        for (int kc = 0; kc < 16; kc++) {
            if (kc < 15) {
                int nb = (kc + 1) & 1;
                float* As = sm + nb * A_STAGE;
                float* Bs = sm + BS_BASE + nb * B_STAGE;
                const float* Ag = features + (size_t)m0 * DD + (kc + 1) * 32;
#pragma unroll
                for (int j = 0; j < 4; j++) {
                    int idx = tid + j * 256;
                    int r = idx >> 3, c4 = idx & 7;
                    cp16(As + r * A_LD + c4 * 4, Ag + (size_t)r * DD + c4 * 4);
                }
                const float* Bg = W1 + (size_t)(kc + 1) * 32 * UU + nc * 128;
#pragma unroll
                for (int j = 0; j < 4; j++) {
                    int idx = tid + j * 256;
                    int r = idx >> 5, c4 = idx & 31;
                    cp16(Bs + r * B_LD + c4 * 4, Bg + (size_t)r * UU + c4 * 4);
                }
                asm volatile("cp.async.commit_group;" ::: "memory");
                asm volatile("cp.async.wait_group 1;" ::: "memory");
            } else {
                asm volatile("cp.async.wait_group 0;" ::: "memory");
            }
            __syncthreads();

            const float* As = sm + (kc & 1) * A_STAGE;
            const float* Bs = sm + BS_BASE + (kc & 1) * B_STAGE;
#pragma unroll
            for (int ks = 0; ks < 4; ks++) {
                const int kk = ks * 8;
                uint32_t a[2][4];
#pragma unroll
                for (int mt = 0; mt < 2; mt++) {
                    const float* ar = As + (mbase + mt * 16) * A_LD + kk;
                    a[mt][0] = f2tf32(ar[g * A_LD + tg]);
                    a[mt][1] = f2tf32(ar[(g + 8) * A_LD + tg]);
                    a[mt][2] = f2tf32(ar[g * A_LD + tg + 4]);
                    a[mt][3] = f2tf32(ar[(g + 8) * A_LD + tg + 4]);
                }
#pragma unroll
                for (int nt = 0; nt < 8; nt++) {
                    int ncol = nbase + nt * 8 + g;
                    uint32_t b0  = f2tf32(Bs[(kk + tg) * B_LD + ncol]);
                    uint32_t b1r = f2tf32(Bs[(kk + tg + 4) * B_LD + ncol]);
                    mma_tf32(c[0][nt], a[0], b0, b1r);
                    mma_tf32(c[1][nt], a[1], b0, b1r);
                }
            }
            __syncthreads();
        }

        // epilogue: tanh + contract with V, accumulate per-row logit partials
#pragma unroll
        for (int mt = 0; mt < 2; mt++) {
            float p0 = 0.f, p1 = 0.f;
#pragma unroll
            for (int nt = 0; nt < 8; nt++) {
                int ncol = nbase + nt * 8 + 2 * tg;
                float ph0 = projh_s[ncol], ph1 = projh_s[ncol + 1];
                float v0 = Vs[ncol], v1 = Vs[ncol + 1];
                p0 += fast_tanh(c[mt][nt][0] + ph0) * v0;
                p0 += fast_tanh(c[mt][nt][1] + ph1) * v1;
                p1 += fast_tanh(c[mt][nt][2] + ph0) * v0;
                p1 += fast_tanh(c[mt][nt][3] + ph1) * v1;
            }
            p0 += __shfl_xor_sync(0xffffffffu, p0, 1);
            p0 += __shfl_xor_sync(0xffffffffu, p0, 2);
            p1 += __shfl_xor_sync(0xffffffffu, p1, 1);
            p1 += __shfl_xor_sync(0xffffffffu, p1, 2);
            if (tg == 0) {
                atomicAdd(&logit_s[mbase + mt * 16 + g], p0);
                atomicAdd(&logit_s[mbase + mt * 16 + 8 + g], p1);
            }
        }
    }
    __syncthreads();
    if (tid < 128) g_logits[m0 + tid] = logit_s[tid] + bv[0];
}

// ---------------------------------------------------------------------------
// K2: softmax over T per batch; writes attn to d_out[16384..]; zeroes context.
// ---------------------------------------------------------------------------
__global__ void softmax_kernel(float* __restrict__ out) {
    int b = blockIdx.x;
    int tid = threadIdx.x;  // 256
    const float* lg = g_logits + b * TT;

    float vals[8];
    float m = -3.4e38f;
#pragma unroll
    for (int j = 0; j < 8; j++) {
        vals[j] = lg[tid + j * 256];
        m = fmaxf(m, vals[j]);
    }
#pragma unroll
    for (int off = 16; off; off >>= 1) m = fmaxf(m, __shfl_xor_sync(0xffffffffu, m, off));

    __shared__ float red[8];
    __shared__ float stat[2];
    int warp = tid >> 5, lane = tid & 31;
    if (lane == 0) red[warp] = m;
    __syncthreads();
    if (tid == 0) {
        float mm = red[0];
        for (int i = 1; i < 8; i++) mm = fmaxf(mm, red[i]);
        stat[0] = mm;
    }
    __syncthreads();
    float smax = stat[0];

    float s = 0.f;
#pragma unroll
    for (int j = 0; j < 8; j++) {
        vals[j] = __expf(vals[j] - smax);
        s += vals[j];
    }
#pragma unroll
    for (int off = 16; off; off >>= 1) s += __shfl_xor_sync(0xffffffffu, s, off);
    if (lane == 0) red[warp] = s;
    __syncthreads();
    if (tid == 0) {
        float ss = 0.f;
        for (int i = 0; i < 8; i++) ss += red[i];
        stat[1] = ss;
    }
    __syncthreads();
    float inv = 1.0f / stat[1];

    float* attn = out + BB * DD + b * TT;
#pragma unroll
    for (int j = 0; j < 8; j++) attn[tid + j * 256] = vals[j] * inv;

    // zero context region (d_out poisoned with 0xAA)
    out[b * DD + tid] = 0.f;
    out[b * DD + 256 + tid] = 0.f;
}

// ---------------------------------------------------------------------------
// K3: context[b,d] = sum_t attn[b,t] * features[b,t,d]
// grid (T/64, B), 128 threads; each thread owns 4 d's (float4). atomicAdd accum.
// ---------------------------------------------------------------------------
__global__ void context_kernel(const float* __restrict__ features,
                               float* __restrict__ out) {
    int b = blockIdx.y;
    int t0 = blockIdx.x * 64;
    int j = threadIdx.x;  // 0..127 -> d = 4j
    const float* fb = features + ((size_t)(b * TT + t0)) * DD + j * 4;
    const float* ap = out + BB * DD + b * TT + t0;  // attn written by K2

    float4 acc = make_float4(0.f, 0.f, 0.f, 0.f);
#pragma unroll 4
    for (int t = 0; t < 64; t++) {
        float w = ap[t];
        float4 f = *reinterpret_cast<const float4*>(fb + (size_t)t * DD);
        acc.x = fmaf(w, f.x, acc.x);
        acc.y = fmaf(w, f.y, acc.y);
        acc.z = fmaf(w, f.z, acc.z);
        acc.w = fmaf(w, f.w, acc.w);
    }
    float* cp = out + b * DD + j * 4;
    atomicAdd(cp + 0, acc.x);
    atomicAdd(cp + 1, acc.y);
    atomicAdd(cp + 2, acc.z);
    atomicAdd(cp + 3, acc.w);
}

// ---------------------------------------------------------------------------
extern "C" void kernel_launch(void* const* d_in, const int* in_sizes, int n_in,
                              void* d_out, int out_size) {
    const float* features = (const float*)d_in[0];
    const float* hidden   = (const float*)d_in[1];
    const float* W1       = (const float*)d_in[2];
    const float* b1       = (const float*)d_in[3];
    const float* W2       = (const float*)d_in[4];
    const float* b2       = (const float*)d_in[5];
    const float* V        = (const float*)d_in[6];
    const float* bv       = (const float*)d_in[7];
    float* out = (float*)d_out;

    cudaFuncSetAttribute(fused_score_kernel,
                         cudaFuncAttributeMaxDynamicSharedMemorySize, SMEM_BYTES);

    projh_kernel<<<BB, UU>>>(hidden, W2, b2);
    fused_score_kernel<<<(BB * TT) / 128, 256, SMEM_BYTES>>>(features, W1, b1, V, bv);
    softmax_kernel<<<BB, 256>>>(out);
    context_kernel<<<dim3(TT / 64, BB), 128>>>(features, out);
}

// round 3
// speedup vs baseline: 1.0559x; 1.0559x over previous
#include <cuda_runtime.h>
#include <cstdint>

#define BB 32
#define TT 2048
#define DD 512
#define UU 512

// Scratch (no device allocation allowed)
__device__ float g_projh[BB * UU];     // hidden@W2 + b2 + b1 (b1 folded)
__device__ float g_logits[BB * TT];
__device__ float g_w1p[UU * DD];       // W1 fragment-packed + tf32-rounded

// ---------------------------------------------------------------------------
// helpers
// ---------------------------------------------------------------------------
__device__ __forceinline__ uint32_t smem_u32(const void* p) {
    uint32_t a;
    asm("{ .reg .u64 t; cvta.to.shared.u64 t, %1; cvt.u32.u64 %0, t; }" : "=r"(a) : "l"(p));
    return a;
}
__device__ __forceinline__ float f2tf(float x) {  // rna tf32, fp32 container
    uint32_t r;
    asm("cvt.rna.tf32.f32 %0, %1;" : "=r"(r) : "f"(x));
    return __uint_as_float(r);
}
__device__ __forceinline__ float fast_tanh(float x) {
    float e = __expf(2.0f * x);
    return 1.0f - __fdividef(2.0f, e + 1.0f);
}
__device__ __forceinline__ void cp16s(uint32_t s, const void* g) {
    asm volatile("cp.async.cg.shared.global [%0], [%1], 16;" :: "r"(s), "l"(g) : "memory");
}
#define CP_COMMIT() asm volatile("cp.async.commit_group;" ::: "memory")

__device__ __forceinline__ void mma_tf32(float* c, const uint32_t* a, uint32_t b0, uint32_t b1) {
    asm volatile(
        "mma.sync.aligned.m16n8k8.row.col.f32.tf32.tf32.f32 "
        "{%0,%1,%2,%3}, {%4,%5,%6,%7}, {%8,%9}, {%0,%1,%2,%3};"
        : "+f"(c[0]), "+f"(c[1]), "+f"(c[2]), "+f"(c[3])
        : "r"(a[0]), "r"(a[1]), "r"(a[2]), "r"(a[3]), "r"(b0), "r"(b1));
}

// ---------------------------------------------------------------------------
// P0: pack W1 [D,U] -> g_w1p, tf32-rounded, mma-fragment order.
// tile = (nsub = u>>7)*16 + (kc = d>>5), 4096 floats per tile:
//   idx_in_tile = (k8*128 + un)*8 + tg*2 + half
//   where k8=(d>>3)&3, tg=d&3, half=(d>>2)&1, un=u&127.
// Inner-loop read: thread (g,tg) does one LDS.64 -> {B[k+tg], B[k+tg+4]}.
// ---------------------------------------------------------------------------
__global__ void pack_w1(const float* __restrict__ W1) {
    int idx = blockIdx.x * 256 + threadIdx.x;  // 0..262143
    int d = idx >> 9, u = idx & 511;
    float v = f2tf(W1[idx]);
    int kc = d >> 5, k8 = (d >> 3) & 3, tg = d & 3, half = (d >> 2) & 1;
    int nsub = u >> 7, un = u & 127;
    g_w1p[(size_t)(nsub * 16 + kc) * 4096 + (k8 * 128 + un) * 8 + tg * 2 + half] = v;
}

// ---------------------------------------------------------------------------
// P1: g_projh[b,u] = hidden[b,:] . W2[:,u] + b2[u] + b1[u]
// ---------------------------------------------------------------------------
__global__ void projh_kernel(const float* __restrict__ hidden,
                             const float* __restrict__ W2,
                             const float* __restrict__ b1,
                             const float* __restrict__ b2) {
    __shared__ float hs[DD];
    int b = blockIdx.x, u = threadIdx.x;
    hs[u] = hidden[b * DD + u];
    __syncthreads();
    float acc = b1[u] + b2[u];
#pragma unroll 16
    for (int d = 0; d < DD; d++) acc = fmaf(hs[d], W2[d * UU + u], acc);
    g_projh[b * UU + u] = acc;
}

// ---------------------------------------------------------------------------
// K1: fused GEMM 128x512x512 + tanh + V-contract.
// 256 threads, warp grid 2(M) x 4(N), warp tile 64x64, nc = two 256-col chunks.
// smem: rawA[2][128*36] | packA[128*32 frag-order] | Bs[2][2*4096] | projh|V|logit
// ---------------------------------------------------------------------------
#define RAW_OFF 0
#define RAW_STAGE_B 18432              // 128*36*4
#define PACK_OFF 36864
#define B_OFF 53248
#define B_STAGE_B 32768                // 2 subtiles * 4096 floats
#define PROJ_OFF 118784
#define V_OFF 120832
#define LOG_OFF 122880
#define SMEM_BYTES 123392

__device__ __forceinline__ void load_chunk(uint32_t sb, const float* __restrict__ features,
                                           int m0, int kc, int nc, int stage, int tid) {
    // A raw: 128 rows x 32 k-floats, row stride 36 floats (conflict-free convert reads)
    uint32_t abase = sb + RAW_OFF + stage * RAW_STAGE_B;
    const float* Ag = features + (size_t)m0 * DD + kc * 32;
#pragma unroll
    for (int j = 0; j < 4; j++) {
        int q = tid + j * 256;         // r = q>>3 (0..127), c16 = q&7
        int r = q >> 3, c16 = q & 7;
        cp16s(abase + (r * 36 + c16 * 4) * 4, Ag + (size_t)r * DD + c16 * 4);
    }
    // B: two packed 16KB subtiles, fully linear
    uint32_t bbase = sb + B_OFF + stage * B_STAGE_B;
#pragma unroll
    for (int sub = 0; sub < 2; sub++) {
        const float* Bg = g_w1p + (size_t)((nc * 2 + sub) * 16 + kc) * 4096;
#pragma unroll
        for (int j = 0; j < 4; j++) {
            int q = tid + j * 256;     // 1024 16B units
            cp16s(bbase + sub * 16384 + q * 16, Bg + q * 4);
        }
    }
    CP_COMMIT();
}

__global__ void __launch_bounds__(256, 1)
fused_score_kernel(const float* __restrict__ features,
                   const float* __restrict__ V,
                   const float* __restrict__ bv) {
    extern __shared__ __align__(128) char smem[];
    const uint32_t sb = smem_u32(smem);
    const int tid = threadIdx.x;
    const int warp = tid >> 5, lane = tid & 31;
    const int g = lane >> 2, tg = lane & 3;
    const int wm = warp >> 2, wn = warp & 3;       // 2 x 4
    const int mbase = wm * 64, nbase = wn * 64;
    const int m0 = blockIdx.x * 128;
    const int bb = m0 >> 11;

    float* projh_s = (float*)(smem + PROJ_OFF);
    float* Vs = (float*)(smem + V_OFF);
    float* logit_s = (float*)(smem + LOG_OFF);
    const float bv0 = bv[0];

    for (int i = tid; i < 512; i += 256) {
        projh_s[i] = g_projh[bb * UU + i];
        Vs[i] = V[i];
    }
    if (tid < 128) logit_s[tid] = 0.f;

    for (int nc = 0; nc < 2; nc++) {
        float c[4][8][4];
#pragma unroll
        for (int i = 0; i < 4; i++)
#pragma unroll
            for (int j = 0; j < 8; j++)
#pragma unroll
                for (int k = 0; k < 4; k++) c[i][j][k] = 0.f;

        load_chunk(sb, features, m0, 0, nc, 0, tid);
        load_chunk(sb, features, m0, 1, nc, 1, tid);

        for (int kc = 0; kc < 16; kc++) {
            const int s = kc & 1;
            if (kc < 15) asm volatile("cp.async.wait_group 1;" ::: "memory");
            else         asm volatile("cp.async.wait_group 0;" ::: "memory");
            __syncthreads();

            // convert rawA -> packA (fragment order, tf32-rounded)
            {
                const float* raw = (const float*)(smem + RAW_OFF + s * RAW_STAGE_B);
                float4* pk = (float4*)(smem + PACK_OFF);
#pragma unroll
                for (int j = 0; j < 4; j++) {
                    int q = tid + j * 256;
                    int mtks = q >> 5, ln = q & 31;
                    int mT = mtks >> 2, ks = mtks & 3;
                    int gq = ln >> 2, tq = ln & 3;
                    int mA = mT * 16 + gq, mB = mA + 8;
                    int k0 = ks * 8 + tq;
                    float4 v;
                    v.x = f2tf(raw[mA * 36 + k0]);
                    v.y = f2tf(raw[mB * 36 + k0]);
                    v.z = f2tf(raw[mA * 36 + k0 + 4]);
                    v.w = f2tf(raw[mB * 36 + k0 + 4]);
                    pk[q] = v;
                }
            }
            __syncthreads();

            // MMA: warp tile 64x64, 128 MMAs per chunk
            const uint4* pk = (const uint4*)(smem + PACK_OFF);
            const float* Bs = (const float*)(smem + B_OFF + s * B_STAGE_B + (wn >> 1) * 16384);
            const int nloc0 = (wn & 1) * 64;
#pragma unroll
            for (int ks = 0; ks < 4; ks++) {
                uint32_t a[4][4];
#pragma unroll
                for (int mt = 0; mt < 4; mt++) {
                    uint4 v = pk[((wm * 4 + mt) * 4 + ks) * 32 + lane];
                    a[mt][0] = v.x; a[mt][1] = v.y; a[mt][2] = v.z; a[mt][3] = v.w;
                }
                uint32_t b[8][2];
#pragma unroll
                for (int nt = 0; nt < 8; nt++) {
                    int nl = nloc0 + nt * 8 + g;
                    const float2 bp = *(const float2*)(Bs + (ks * 128 + nl) * 8 + tg * 2);
                    b[nt][0] = __float_as_uint(bp.x);
                    b[nt][1] = __float_as_uint(bp.y);
                }
#pragma unroll
                for (int mt = 0; mt < 4; mt++)
#pragma unroll
                    for (int nt = 0; nt < 8; nt++)
                        mma_tf32(c[mt][nt], a[mt], b[nt][0], b[nt][1]);
            }
            __syncthreads();
            if (kc + 2 < 16) load_chunk(sb, features, m0, kc + 2, nc, s, tid);
        }

        // epilogue: tanh(+projh) . V
#pragma unroll
        for (int mt = 0; mt < 4; mt++) {
            float p0 = 0.f, p1 = 0.f;
#pragma unroll
            for (int nt = 0; nt < 8; nt++) {
                int u0 = nc * 256 + nbase + nt * 8 + 2 * tg;
                float ph0 = projh_s[u0], ph1 = projh_s[u0 + 1];
                float v0 = Vs[u0], v1 = Vs[u0 + 1];
                p0 += fast_tanh(c[mt][nt][0] + ph0) * v0;
                p0 += fast_tanh(c[mt][nt][1] + ph1) * v1;
                p1 += fast_tanh(c[mt][nt][2] + ph0) * v0;
                p1 += fast_tanh(c[mt][nt][3] + ph1) * v1;
            }
            p0 += __shfl_xor_sync(0xffffffffu, p0, 1);
            p0 += __shfl_xor_sync(0xffffffffu, p0, 2);
            p1 += __shfl_xor_sync(0xffffffffu, p1, 1);
            p1 += __shfl_xor_sync(0xffffffffu, p1, 2);
            if (tg == 0) {
                atomicAdd(&logit_s[mbase + mt * 16 + g], p0);
                atomicAdd(&logit_s[mbase + mt * 16 + 8 + g], p1);
            }
        }
        __syncthreads();   // logit_s consistent; Bs/packA free for next nc
    }
    if (tid < 128) g_logits[m0 + tid] = logit_s[tid] + bv0;
}

// ---------------------------------------------------------------------------
// K2: softmax over T per batch; writes attn; zeroes context region.
// ---------------------------------------------------------------------------
__global__ void softmax_kernel(float* __restrict__ out) {
    int b = blockIdx.x;
    int tid = threadIdx.x;  // 256
    const float* lg = g_logits + b * TT;

    float vals[8];
    float m = -3.4e38f;
#pragma unroll
    for (int j = 0; j < 8; j++) {
        vals[j] = lg[tid + j * 256];
        m = fmaxf(m, vals[j]);
    }
#pragma unroll
    for (int off = 16; off; off >>= 1) m = fmaxf(m, __shfl_xor_sync(0xffffffffu, m, off));

    __shared__ float red[8];
    __shared__ float stat[2];
    int warp = tid >> 5, lane = tid & 31;
    if (lane == 0) red[warp] = m;
    __syncthreads();
    if (tid == 0) {
        float mm = red[0];
        for (int i = 1; i < 8; i++) mm = fmaxf(mm, red[i]);
        stat[0] = mm;
    }
    __syncthreads();
    float smax = stat[0];

    float s = 0.f;
#pragma unroll
    for (int j = 0; j < 8; j++) {
        vals[j] = __expf(vals[j] - smax);
        s += vals[j];
    }
#pragma unroll
    for (int off = 16; off; off >>= 1) s += __shfl_xor_sync(0xffffffffu, s, off);
    if (lane == 0) red[warp] = s;
    __syncthreads();
    if (tid == 0) {
        float ss = 0.f;
        for (int i = 0; i < 8; i++) ss += red[i];
        stat[1] = ss;
    }
    __syncthreads();
    float inv = 1.0f / stat[1];

    float* attn = out + BB * DD + b * TT;
#pragma unroll
    for (int j = 0; j < 8; j++) attn[tid + j * 256] = vals[j] * inv;

    out[b * DD + tid] = 0.f;
    out[b * DD + 256 + tid] = 0.f;
}

// ---------------------------------------------------------------------------
// K3: context[b,d] = sum_t attn[b,t] * features[b,t,d]
// ---------------------------------------------------------------------------
__global__ void context_kernel(const float* __restrict__ features,
                               float* __restrict__ out) {
    int b = blockIdx.y;
    int t0 = blockIdx.x * 32;
    int j = threadIdx.x;  // d = 4j
    const float* fb = features + ((size_t)(b * TT + t0)) * DD + j * 4;
    const float* ap = out + BB * DD + b * TT + t0;

    float4 acc = make_float4(0.f, 0.f, 0.f, 0.f);
#pragma unroll 4
    for (int t = 0; t < 32; t++) {
        float w = ap[t];
        float4 f = *reinterpret_cast<const float4*>(fb + (size_t)t * DD);
        acc.x = fmaf(w, f.x, acc.x);
        acc.y = fmaf(w, f.y, acc.y);
        acc.z = fmaf(w, f.z, acc.z);
        acc.w = fmaf(w, f.w, acc.w);
    }
    float* cp = out + b * DD + j * 4;
    atomicAdd(cp + 0, acc.x);
    atomicAdd(cp + 1, acc.y);
    atomicAdd(cp + 2, acc.z);
    atomicAdd(cp + 3, acc.w);
}

// ---------------------------------------------------------------------------
extern "C" void kernel_launch(void* const* d_in, const int* in_sizes, int n_in,
                              void* d_out, int out_size) {
    const float* features = (const float*)d_in[0];
    const float* hidden   = (const float*)d_in[1];
    const float* W1       = (const float*)d_in[2];
    const float* b1       = (const float*)d_in[3];
    const float* W2       = (const float*)d_in[4];
    const float* b2       = (const float*)d_in[5];
    const float* V        = (const float*)d_in[6];
    const float* bv       = (const float*)d_in[7];
    float* out = (float*)d_out;

    cudaFuncSetAttribute(fused_score_kernel,
                         cudaFuncAttributeMaxDynamicSharedMemorySize, SMEM_BYTES);

    pack_w1<<<1024, 256>>>(W1);
    projh_kernel<<<BB, UU>>>(hidden, W2, b1, b2);
    fused_score_kernel<<<(BB * TT) / 128, 256, SMEM_BYTES>>>(features, V, bv);
    softmax_kernel<<<BB, 256>>>(out);
    context_kernel<<<dim3(TT / 32, BB), 128>>>(features, out);
}

// round 4
// speedup vs baseline: 1.4473x; 1.3706x over previous
#include <cuda_runtime.h>
#include <cuda_fp16.h>
#include <cstdint>

#define BB 32
#define TT 2048
#define DD 512
#define UU 512

// Scratch (no device allocation allowed)
__device__ float g_projh[BB * UU];       // hidden@W2 + b2 + b1 (b1 folded)
__device__ float g_logits[BB * TT];
__device__ __half g_w1p[UU * DD];        // W1 fragment-packed fp16 (rn)

// ---------------------------------------------------------------------------
// helpers
// ---------------------------------------------------------------------------
__device__ __forceinline__ uint32_t smem_u32(const void* p) {
    uint32_t a;
    asm("{ .reg .u64 t; cvta.to.shared.u64 t, %1; cvt.u32.u64 %0, t; }" : "=r"(a) : "l"(p));
    return a;
}
__device__ __forceinline__ float fast_tanh(float x) {
    float e = __expf(2.0f * x);
    return 1.0f - __fdividef(2.0f, e + 1.0f);
}
__device__ __forceinline__ void cp16s(uint32_t s, const void* g) {
    asm volatile("cp.async.cg.shared.global [%0], [%1], 16;" :: "r"(s), "l"(g) : "memory");
}
#define CP_COMMIT() asm volatile("cp.async.commit_group;" ::: "memory")

__device__ __forceinline__ uint32_t packh2(float lo, float hi) {
    uint32_t r;
    asm("cvt.rn.f16x2.f32 %0, %1, %2;" : "=r"(r) : "f"(hi), "f"(lo));
    return r;
}
__device__ __forceinline__ void mma_f16(float* c, const uint32_t* a, uint32_t b0, uint32_t b1) {
    asm volatile(
        "mma.sync.aligned.m16n8k16.row.col.f32.f16.f16.f32 "
        "{%0,%1,%2,%3}, {%4,%5,%6,%7}, {%8,%9}, {%0,%1,%2,%3};"
        : "+f"(c[0]), "+f"(c[1]), "+f"(c[2]), "+f"(c[3])
        : "r"(a[0]), "r"(a[1]), "r"(a[2]), "r"(a[3]), "r"(b0), "r"(b1));
}

// ---------------------------------------------------------------------------
// P0: pack W1 [D,U] -> g_w1p (fp16, m16n8k16 B-fragment order).
// tile = (nsub=u>>7)*16 + (kc=d>>5); within tile (4096 halves):
//   ks=(d>>4)&1, r=d&15, tg=(r&7)>>1, hidx=(r>>3)*2+(r&1), un=u&127
//   off = ((ks*128+un)*4 + tg)*4 + hidx
// Inner loop: thread (g,tg) does one LDS.64 -> {b0={B[2tg],B[2tg+1]}, b1={B[2tg+8],B[2tg+9]}}
// ---------------------------------------------------------------------------
__global__ void pack_w1(const float* __restrict__ W1) {
    int idx = blockIdx.x * 256 + threadIdx.x;  // 0..262143
    int d = idx >> 9, u = idx & 511;
    __half v = __float2half_rn(W1[idx]);
    int kc = d >> 5, ks = (d >> 4) & 1, r = d & 15;
    int tg = (r & 7) >> 1, hidx = (r >> 3) * 2 + (r & 1);
    int nsub = u >> 7, un = u & 127;
    g_w1p[(size_t)(nsub * 16 + kc) * 4096 + ((ks * 128 + un) * 4 + tg) * 4 + hidx] = v;
}

// ---------------------------------------------------------------------------
// P1: g_projh[b,u] = hidden[b,:] . W2[:,u] + b2[u] + b1[u]
// ---------------------------------------------------------------------------
__global__ void projh_kernel(const float* __restrict__ hidden,
                             const float* __restrict__ W2,
                             const float* __restrict__ b1,
                             const float* __restrict__ b2) {
    __shared__ float hs[DD];
    int b = blockIdx.x, u = threadIdx.x;
    hs[u] = hidden[b * DD + u];
    __syncthreads();
    float acc = b1[u] + b2[u];
#pragma unroll 16
    for (int d = 0; d < DD; d++) acc = fmaf(hs[d], W2[d * UU + u], acc);
    g_projh[b * UU + u] = acc;
}

// ---------------------------------------------------------------------------
// K1: fused GEMM 128x512x512 (fp16 MMA, fp32 accum) + tanh + V-contract.
// 256 threads, warp grid 2(M) x 4(N), warp tile 64x64, nc = two 256-col chunks.
// smem: rawA[2][128*36 f32] | packA[8KB fp16 frags] | Bs[2][16KB fp16] | projh|V|logit
// ---------------------------------------------------------------------------
#define RAW_OFF 0
#define RAW_STAGE_B 18432              // 128*36*4
#define PACK_OFF 36864                 // 8192 B
#define B_OFF 45056
#define B_STAGE_B 16384                // 2 subtiles * 8KB fp16
#define PROJ_OFF 77824
#define V_OFF 79872
#define LOG_OFF 81920
#define SMEM_BYTES 82432

__device__ __forceinline__ void load_chunk(uint32_t sb, const float* __restrict__ features,
                                           int m0, int kc, int nc, int stage, int tid) {
    // A raw fp32: 128 rows x 32 k, row stride 36 floats
    uint32_t abase = sb + RAW_OFF + stage * RAW_STAGE_B;
    const float* Ag = features + (size_t)m0 * DD + kc * 32;
#pragma unroll
    for (int j = 0; j < 4; j++) {
        int q = tid + j * 256;         // r = q>>3 (0..127), c16 = q&7
        int r = q >> 3, c16 = q & 7;
        cp16s(abase + (r * 36 + c16 * 4) * 4, Ag + (size_t)r * DD + c16 * 4);
    }
    // B fp16: two packed 8KB subtiles, fully linear
    uint32_t bbase = sb + B_OFF + stage * B_STAGE_B;
#pragma unroll
    for (int sub = 0; sub < 2; sub++) {
        const __half* Bg = g_w1p + (size_t)((nc * 2 + sub) * 16 + kc) * 4096;
#pragma unroll
        for (int j = 0; j < 2; j++) {
            int q = tid + j * 256;     // 512 16B units
            cp16s(bbase + sub * 8192 + q * 16, Bg + q * 8);
        }
    }
    CP_COMMIT();
}

__global__ void __launch_bounds__(256, 1)
fused_score_kernel(const float* __restrict__ features,
                   const float* __restrict__ V,
                   const float* __restrict__ bv) {
    extern __shared__ __align__(128) char smem[];
    const uint32_t sb = smem_u32(smem);
    const int tid = threadIdx.x;
    const int warp = tid >> 5, lane = tid & 31;
    const int g = lane >> 2, tg = lane & 3;
    const int wm = warp >> 2, wn = warp & 3;       // 2 x 4
    const int mbase = wm * 64, nbase = wn * 64;
    const int m0 = blockIdx.x * 128;
    const int bb = m0 >> 11;

    float* projh_s = (float*)(smem + PROJ_OFF);
    float* Vs = (float*)(smem + V_OFF);
    float* logit_s = (float*)(smem + LOG_OFF);
    const float bv0 = bv[0];

    for (int i = tid; i < 512; i += 256) {
        projh_s[i] = g_projh[bb * UU + i];
        Vs[i] = V[i];
    }
    if (tid < 128) logit_s[tid] = 0.f;

    for (int nc = 0; nc < 2; nc++) {
        float c[4][8][4];
#pragma unroll
        for (int i = 0; i < 4; i++)
#pragma unroll
            for (int j = 0; j < 8; j++)
#pragma unroll
                for (int k = 0; k < 4; k++) c[i][j][k] = 0.f;

        load_chunk(sb, features, m0, 0, nc, 0, tid);
        load_chunk(sb, features, m0, 1, nc, 1, tid);

        for (int kc = 0; kc < 16; kc++) {
            const int s = kc & 1;
            if (kc < 15) asm volatile("cp.async.wait_group 1;" ::: "memory");
            else         asm volatile("cp.async.wait_group 0;" ::: "memory");
            __syncthreads();

            // convert rawA fp32 -> packA fp16 fragments (m16n8k16 A order)
            {
                const float* raw = (const float*)(smem + RAW_OFF + s * RAW_STAGE_B);
                uint4* pk = (uint4*)(smem + PACK_OFF);
#pragma unroll
                for (int j = 0; j < 2; j++) {
                    int q = tid + j * 256;          // 512 fragment-quads
                    int ln = q & 31, mtks = q >> 5;
                    int mt = mtks >> 1, ks = mtks & 1;
                    int gq = ln >> 2, tq = ln & 3;
                    int mA = mt * 16 + gq, mB = mA + 8;
                    int k0 = ks * 16 + 2 * tq;
                    float2 xA0 = *(const float2*)(raw + mA * 36 + k0);
                    float2 xB0 = *(const float2*)(raw + mB * 36 + k0);
                    float2 xA1 = *(const float2*)(raw + mA * 36 + k0 + 8);
                    float2 xB1 = *(const float2*)(raw + mB * 36 + k0 + 8);
                    uint4 v;
                    v.x = packh2(xA0.x, xA0.y);
                    v.y = packh2(xB0.x, xB0.y);
                    v.z = packh2(xA1.x, xA1.y);
                    v.w = packh2(xB1.x, xB1.y);
                    pk[q] = v;
                }
            }
            __syncthreads();

            // MMA: warp tile 64x64, 64 m16n8k16 MMAs per chunk
            const uint4* pk = (const uint4*)(smem + PACK_OFF);
            const char* Bs = smem + B_OFF + s * B_STAGE_B + (wn >> 1) * 8192;
            const int nloc0 = (wn & 1) * 64;
#pragma unroll
            for (int ks = 0; ks < 2; ks++) {
                uint32_t a[4][4];
#pragma unroll
                for (int mt = 0; mt < 4; mt++) {
                    uint4 v = pk[((wm * 4 + mt) * 2 + ks) * 32 + lane];
                    a[mt][0] = v.x; a[mt][1] = v.y; a[mt][2] = v.z; a[mt][3] = v.w;
                }
                uint32_t b[8][2];
#pragma unroll
                for (int nt = 0; nt < 8; nt++) {
                    int nl = nloc0 + nt * 8 + g;
                    uint2 bp = *(const uint2*)(Bs + ((ks * 128 + nl) * 4 + tg) * 8);
                    b[nt][0] = bp.x; b[nt][1] = bp.y;
                }
#pragma unroll
                for (int mt = 0; mt < 4; mt++)
#pragma unroll
                    for (int nt = 0; nt < 8; nt++)
                        mma_f16(c[mt][nt], a[mt], b[nt][0], b[nt][1]);
            }
            __syncthreads();
            if (kc + 2 < 16) load_chunk(sb, features, m0, kc + 2, nc, s, tid);
        }

        // epilogue: tanh(+projh) . V   (C fragment layout same as tf32 path)
#pragma unroll
        for (int mt = 0; mt < 4; mt++) {
            float p0 = 0.f, p1 = 0.f;
#pragma unroll
            for (int nt = 0; nt < 8; nt++) {
                int u0 = nc * 256 + nbase + nt * 8 + 2 * tg;
                float ph0 = projh_s[u0], ph1 = projh_s[u0 + 1];
                float v0 = Vs[u0], v1 = Vs[u0 + 1];
                p0 += fast_tanh(c[mt][nt][0] + ph0) * v0;
                p0 += fast_tanh(c[mt][nt][1] + ph1) * v1;
                p1 += fast_tanh(c[mt][nt][2] + ph0) * v0;
                p1 += fast_tanh(c[mt][nt][3] + ph1) * v1;
            }
            p0 += __shfl_xor_sync(0xffffffffu, p0, 1);
            p0 += __shfl_xor_sync(0xffffffffu, p0, 2);
            p1 += __shfl_xor_sync(0xffffffffu, p1, 1);
            p1 += __shfl_xor_sync(0xffffffffu, p1, 2);
            if (tg == 0) {
                atomicAdd(&logit_s[mbase + mt * 16 + g], p0);
                atomicAdd(&logit_s[mbase + mt * 16 + 8 + g], p1);
            }
        }
        __syncthreads();
    }
    if (tid < 128) g_logits[m0 + tid] = logit_s[tid] + bv0;
}

// ---------------------------------------------------------------------------
// K2: softmax over T per batch; writes attn; zeroes context region.
// ---------------------------------------------------------------------------
__global__ void softmax_kernel(float* __restrict__ out) {
    int b = blockIdx.x;
    int tid = threadIdx.x;  // 256
    const float* lg = g_logits + b * TT;

    float vals[8];
    float m = -3.4e38f;
#pragma unroll
    for (int j = 0; j < 8; j++) {
        vals[j] = lg[tid + j * 256];
        m = fmaxf(m, vals[j]);
    }
#pragma unroll
    for (int off = 16; off; off >>= 1) m = fmaxf(m, __shfl_xor_sync(0xffffffffu, m, off));

    __shared__ float red[8];
    __shared__ float stat[2];
    int warp = tid >> 5, lane = tid & 31;
    if (lane == 0) red[warp] = m;
    __syncthreads();
    if (tid == 0) {
        float mm = red[0];
        for (int i = 1; i < 8; i++) mm = fmaxf(mm, red[i]);
        stat[0] = mm;
    }
    __syncthreads();
    float smax = stat[0];

    float s = 0.f;
#pragma unroll
    for (int j = 0; j < 8; j++) {
        vals[j] = __expf(vals[j] - smax);
        s += vals[j];
    }
#pragma unroll
    for (int off = 16; off; off >>= 1) s += __shfl_xor_sync(0xffffffffu, s, off);
    if (lane == 0) red[warp] = s;
    __syncthreads();
    if (tid == 0) {
        float ss = 0.f;
        for (int i = 0; i < 8; i++) ss += red[i];
        stat[1] = ss;
    }
    __syncthreads();
    float inv = 1.0f / stat[1];

    float* attn = out + BB * DD + b * TT;
#pragma unroll
    for (int j = 0; j < 8; j++) attn[tid + j * 256] = vals[j] * inv;

    out[b * DD + tid] = 0.f;
    out[b * DD + 256 + tid] = 0.f;
}

// ---------------------------------------------------------------------------
// K3: context[b,d] = sum_t attn[b,t] * features[b,t,d]
// ---------------------------------------------------------------------------
__global__ void context_kernel(const float* __restrict__ features,
                               float* __restrict__ out) {
    int b = blockIdx.y;
    int t0 = blockIdx.x * 32;
    int j = threadIdx.x;  // d = 4j
    const float* fb = features + ((size_t)(b * TT + t0)) * DD + j * 4;
    const float* ap = out + BB * DD + b * TT + t0;

    float4 acc = make_float4(0.f, 0.f, 0.f, 0.f);
#pragma unroll 4
    for (int t = 0; t < 32; t++) {
        float w = ap[t];
        float4 f = *reinterpret_cast<const float4*>(fb + (size_t)t * DD);
        acc.x = fmaf(w, f.x, acc.x);
        acc.y = fmaf(w, f.y, acc.y);
        acc.z = fmaf(w, f.z, acc.z);
        acc.w = fmaf(w, f.w, acc.w);
    }
    float* cp = out + b * DD + j * 4;
    atomicAdd(cp + 0, acc.x);
    atomicAdd(cp + 1, acc.y);
    atomicAdd(cp + 2, acc.z);
    atomicAdd(cp + 3, acc.w);
}

// ---------------------------------------------------------------------------
extern "C" void kernel_launch(void* const* d_in, const int* in_sizes, int n_in,
                              void* d_out, int out_size) {
    const float* features = (const float*)d_in[0];
    const float* hidden   = (const float*)d_in[1];
    const float* W1       = (const float*)d_in[2];
    const float* b1       = (const float*)d_in[3];
    const float* W2       = (const float*)d_in[4];
    const float* b2       = (const float*)d_in[5];
    const float* V        = (const float*)d_in[6];
    const float* bv       = (const float*)d_in[7];
    float* out = (float*)d_out;

    cudaFuncSetAttribute(fused_score_kernel,
                         cudaFuncAttributeMaxDynamicSharedMemorySize, SMEM_BYTES);

    pack_w1<<<1024, 256>>>(W1);
    projh_kernel<<<BB, UU>>>(hidden, W2, b1, b2);
    fused_score_kernel<<<(BB * TT) / 128, 256, SMEM_BYTES>>>(features, V, bv);
    softmax_kernel<<<BB, 256>>>(out);
    context_kernel<<<dim3(TT / 32, BB), 128>>>(features, out);
}

// round 5
// speedup vs baseline: 1.5893x; 1.0981x over previous
#include <cuda_runtime.h>
#include <cuda_fp16.h>
#include <cstdint>

#define BB 32
#define TT 2048
#define DD 512
#define UU 512

// Scratch (no device allocation allowed)
__device__ float g_projh[BB * UU];       // hidden@W2 + b2 + b1 (b1 folded)
__device__ float g_logits[BB * TT];
__device__ __half g_w1p[UU * DD];        // W1 fragment-packed fp16 (rn)

// ---------------------------------------------------------------------------
// helpers
// ---------------------------------------------------------------------------
__device__ __forceinline__ uint32_t smem_u32(const void* p) {
    uint32_t a;
    asm("{ .reg .u64 t; cvta.to.shared.u64 t, %1; cvt.u32.u64 %0, t; }" : "=r"(a) : "l"(p));
    return a;
}
__device__ __forceinline__ float tanhap(float x) {
    float y;
    asm("tanh.approx.f32 %0, %1;" : "=f"(y) : "f"(x));
    return y;
}
__device__ __forceinline__ void cp16s(uint32_t s, const void* g) {
    asm volatile("cp.async.cg.shared.global [%0], [%1], 16;" :: "r"(s), "l"(g) : "memory");
}
#define CP_COMMIT() asm volatile("cp.async.commit_group;" ::: "memory")

__device__ __forceinline__ uint32_t packh2(float lo, float hi) {
    uint32_t r;
    asm("cvt.rn.f16x2.f32 %0, %1, %2;" : "=r"(r) : "f"(hi), "f"(lo));
    return r;
}
__device__ __forceinline__ void mma_f16(float* c, const uint32_t* a, uint32_t b0, uint32_t b1) {
    asm volatile(
        "mma.sync.aligned.m16n8k16.row.col.f32.f16.f16.f32 "
        "{%0,%1,%2,%3}, {%4,%5,%6,%7}, {%8,%9}, {%0,%1,%2,%3};"
        : "+f"(c[0]), "+f"(c[1]), "+f"(c[2]), "+f"(c[3])
        : "r"(a[0]), "r"(a[1]), "r"(a[2]), "r"(a[3]), "r"(b0), "r"(b1));
}

// ---------------------------------------------------------------------------
// P0: pack W1 [D,U] -> g_w1p (fp16, m16n8k16 B-fragment order).
// tile = (nsub=u>>7)*16 + (kc=d>>5); within tile (4096 halves):
//   ks=(d>>4)&1, r=d&15, tg=(r&7)>>1, hidx=(r>>3)*2+(r&1), un=u&127
//   off = ((ks*128+un)*4 + tg)*4 + hidx
// ---------------------------------------------------------------------------
__global__ void pack_w1(const float* __restrict__ W1) {
    int idx = blockIdx.x * 256 + threadIdx.x;  // 0..262143
    int d = idx >> 9, u = idx & 511;
    __half v = __float2half_rn(W1[idx]);
    int kc = d >> 5, ks = (d >> 4) & 1, r = d & 15;
    int tg = (r & 7) >> 1, hidx = (r >> 3) * 2 + (r & 1);
    int nsub = u >> 7, un = u & 127;
    g_w1p[(size_t)(nsub * 16 + kc) * 4096 + ((ks * 128 + un) * 4 + tg) * 4 + hidx] = v;
}

// ---------------------------------------------------------------------------
// P1: g_projh[b,u] = hidden[b,:] . W2[:,u] + b2[u] + b1[u]
// ---------------------------------------------------------------------------
__global__ void projh_kernel(const float* __restrict__ hidden,
                             const float* __restrict__ W2,
                             const float* __restrict__ b1,
                             const float* __restrict__ b2) {
    __shared__ float hs[DD];
    int b = blockIdx.x, u = threadIdx.x;
    hs[u] = hidden[b * DD + u];
    __syncthreads();
    float acc = b1[u] + b2[u];
#pragma unroll 16
    for (int d = 0; d < DD; d++) acc = fmaf(hs[d], W2[d * UU + u], acc);
    g_projh[b * UU + u] = acc;
}

// ---------------------------------------------------------------------------
// K1: fused GEMM 128x512x512 (fp16 MMA, fp32 accum) + tanh + V-contract.
// Phase 1: convert full A tile fp32->fp16 fragments into persistent 128KB smem.
// Phase 2: 2 nc passes over N=512; inner loop = pure MMA + B loads.
// smem: packA[128KB] | Araw[2][18KB] | B[3][16KB] | projh | V | logit
// ---------------------------------------------------------------------------
#define PACKA_OFF 0                    // 131072 B (16 chunks * 8192)
#define ARAW_OFF 131072
#define ARAW_STAGE_B 18432             // 128*36*4
#define B_OFF 167936
#define B_STAGE_B 16384
#define PROJ_OFF 217088
#define V_OFF 219136
#define LOG_OFF 221184
#define SMEM_BYTES 221696

__device__ __forceinline__ void load_araw(uint32_t sb, const float* __restrict__ features,
                                          int m0, int kc, int stage, int tid) {
    uint32_t abase = sb + ARAW_OFF + stage * ARAW_STAGE_B;
    const float* Ag = features + (size_t)m0 * DD + kc * 32;
#pragma unroll
    for (int j = 0; j < 4; j++) {
        int q = tid + j * 256;         // r = q>>3 (0..127), c16 = q&7
        int r = q >> 3, c16 = q & 7;
        cp16s(abase + (r * 36 + c16 * 4) * 4, Ag + (size_t)r * DD + c16 * 4);
    }
    CP_COMMIT();
}

__device__ __forceinline__ void load_b(uint32_t sb, int kc, int nc, int stage, int tid) {
    uint32_t bbase = sb + B_OFF + stage * B_STAGE_B;
#pragma unroll
    for (int sub = 0; sub < 2; sub++) {
        const __half* Bg = g_w1p + (size_t)((nc * 2 + sub) * 16 + kc) * 4096;
#pragma unroll
        for (int j = 0; j < 2; j++) {
            int q = tid + j * 256;     // 512 16B units
            cp16s(bbase + sub * 8192 + q * 16, Bg + q * 8);
        }
    }
    CP_COMMIT();
}

__global__ void __launch_bounds__(256, 1)
fused_score_kernel(const float* __restrict__ features,
                   const float* __restrict__ V,
                   const float* __restrict__ bv) {
    extern __shared__ __align__(128) char smem[];
    const uint32_t sb = smem_u32(smem);
    const int tid = threadIdx.x;
    const int warp = tid >> 5, lane = tid & 31;
    const int g = lane >> 2, tg = lane & 3;
    const int wm = warp >> 2, wn = warp & 3;       // 2 x 4
    const int mbase = wm * 64, nbase = wn * 64;
    const int m0 = blockIdx.x * 128;
    const int bb = m0 >> 11;

    float* projh_s = (float*)(smem + PROJ_OFF);
    float* Vs = (float*)(smem + V_OFF);
    float* logit_s = (float*)(smem + LOG_OFF);
    const float bv0 = bv[0];

    for (int i = tid; i < 512; i += 256) {
        projh_s[i] = g_projh[bb * UU + i];
        Vs[i] = V[i];
    }
    if (tid < 128) logit_s[tid] = 0.f;

    // ---------------- Phase 1: convert A tile to fp16 fragments ----------------
    load_araw(sb, features, m0, 0, 0, tid);
    load_araw(sb, features, m0, 1, 1, tid);
    for (int kc = 0; kc < 16; kc++) {
        const int s = kc & 1;
        if (kc < 15) asm volatile("cp.async.wait_group 1;" ::: "memory");
        else         asm volatile("cp.async.wait_group 0;" ::: "memory");
        __syncthreads();
        {
            const float* raw = (const float*)(smem + ARAW_OFF + s * ARAW_STAGE_B);
            uint4* pk = (uint4*)(smem + PACKA_OFF) + kc * 512;
#pragma unroll
            for (int j = 0; j < 2; j++) {
                int q = tid + j * 256;          // 512 fragment-quads
                int ln = q & 31, mtks = q >> 5;
                int mt = mtks >> 1, ks = mtks & 1;
                int gq = ln >> 2, tq = ln & 3;
                int mA = mt * 16 + gq, mB = mA + 8;
                int k0 = ks * 16 + 2 * tq;
                float2 xA0 = *(const float2*)(raw + mA * 36 + k0);
                float2 xB0 = *(const float2*)(raw + mB * 36 + k0);
                float2 xA1 = *(const float2*)(raw + mA * 36 + k0 + 8);
                float2 xB1 = *(const float2*)(raw + mB * 36 + k0 + 8);
                uint4 v;
                v.x = packh2(xA0.x, xA0.y);
                v.y = packh2(xB0.x, xB0.y);
                v.z = packh2(xA1.x, xA1.y);
                v.w = packh2(xB1.x, xB1.y);
                pk[q] = v;
            }
        }
        __syncthreads();
        if (kc + 2 < 16) load_araw(sb, features, m0, kc + 2, s, tid);
    }

    // ---------------- Phase 2: MMA over 2 nc passes ----------------
    // prefetch B(nc=0) chunks 0..2
    load_b(sb, 0, 0, 0, tid);
    load_b(sb, 1, 0, 1, tid);
    load_b(sb, 2, 0, 2, tid);

    const uint4* pkA = (const uint4*)(smem + PACKA_OFF);

    for (int nc = 0; nc < 2; nc++) {
        float c[4][8][4];
#pragma unroll
        for (int i = 0; i < 4; i++)
#pragma unroll
            for (int j = 0; j < 8; j++)
#pragma unroll
                for (int k = 0; k < 4; k++) c[i][j][k] = 0.f;

        for (int kc = 0; kc < 16; kc++) {
            const int s = kc % 3;
            if (kc < 14)      asm volatile("cp.async.wait_group 2;" ::: "memory");
            else if (kc == 14) asm volatile("cp.async.wait_group 1;" ::: "memory");
            else               asm volatile("cp.async.wait_group 0;" ::: "memory");
            __syncthreads();

            const char* Bs = smem + B_OFF + s * B_STAGE_B + (wn >> 1) * 8192;
            const int nloc0 = (wn & 1) * 64;
#pragma unroll
            for (int ks = 0; ks < 2; ks++) {
                uint32_t a[4][4];
#pragma unroll
                for (int mt = 0; mt < 4; mt++) {
                    uint4 v = pkA[kc * 512 + ((wm * 4 + mt) * 2 + ks) * 32 + lane];
                    a[mt][0] = v.x; a[mt][1] = v.y; a[mt][2] = v.z; a[mt][3] = v.w;
                }
                uint32_t b[8][2];
#pragma unroll
                for (int nt = 0; nt < 8; nt++) {
                    int nl = nloc0 + nt * 8 + g;
                    uint2 bp = *(const uint2*)(Bs + ((ks * 128 + nl) * 4 + tg) * 8);
                    b[nt][0] = bp.x; b[nt][1] = bp.y;
                }
#pragma unroll
                for (int mt = 0; mt < 4; mt++)
#pragma unroll
                    for (int nt = 0; nt < 8; nt++)
                        mma_f16(c[mt][nt], a[mt], b[nt][0], b[nt][1]);
            }
            __syncthreads();
            if (kc + 3 < 16) load_b(sb, kc + 3, nc, (kc + 3) % 3, tid);
        }

        // prefetch next nc's B under the epilogue
        if (nc == 0) {
            load_b(sb, 0, 1, 0, tid);
            load_b(sb, 1, 1, 1, tid);
            load_b(sb, 2, 1, 2, tid);
        }

        // epilogue: tanh(+projh) . V
#pragma unroll
        for (int mt = 0; mt < 4; mt++) {
            float p0 = 0.f, p1 = 0.f;
#pragma unroll
            for (int nt = 0; nt < 8; nt++) {
                int u0 = nc * 256 + nbase + nt * 8 + 2 * tg;
                float ph0 = projh_s[u0], ph1 = projh_s[u0 + 1];
                float v0 = Vs[u0], v1 = Vs[u0 + 1];
                p0 += tanhap(c[mt][nt][0] + ph0) * v0;
                p0 += tanhap(c[mt][nt][1] + ph1) * v1;
                p1 += tanhap(c[mt][nt][2] + ph0) * v0;
                p1 += tanhap(c[mt][nt][3] + ph1) * v1;
            }
            p0 += __shfl_xor_sync(0xffffffffu, p0, 1);
            p0 += __shfl_xor_sync(0xffffffffu, p0, 2);
            p1 += __shfl_xor_sync(0xffffffffu, p1, 1);
            p1 += __shfl_xor_sync(0xffffffffu, p1, 2);
            if (tg == 0) {
                atomicAdd(&logit_s[mbase + mt * 16 + g], p0);
                atomicAdd(&logit_s[mbase + mt * 16 + 8 + g], p1);
            }
        }
    }
    __syncthreads();
    if (tid < 128) g_logits[m0 + tid] = logit_s[tid] + bv0;
}

// ---------------------------------------------------------------------------
// K2: softmax over T per batch; writes attn; zeroes context region.
// ---------------------------------------------------------------------------
__global__ void softmax_kernel(float* __restrict__ out) {
    int b = blockIdx.x;
    int tid = threadIdx.x;  // 256
    const float* lg = g_logits + b * TT;

    float vals[8];
    float m = -3.4e38f;
#pragma unroll
    for (int j = 0; j < 8; j++) {
        vals[j] = lg[tid + j * 256];
        m = fmaxf(m, vals[j]);
    }
#pragma unroll
    for (int off = 16; off; off >>= 1) m = fmaxf(m, __shfl_xor_sync(0xffffffffu, m, off));

    __shared__ float red[8];
    __shared__ float stat[2];
    int warp = tid >> 5, lane = tid & 31;
    if (lane == 0) red[warp] = m;
    __syncthreads();
    if (tid == 0) {
        float mm = red[0];
        for (int i = 1; i < 8; i++) mm = fmaxf(mm, red[i]);
        stat[0] = mm;
    }
    __syncthreads();
    float smax = stat[0];

    float s = 0.f;
#pragma unroll
    for (int j = 0; j < 8; j++) {
        vals[j] = __expf(vals[j] - smax);
        s += vals[j];
    }
#pragma unroll
    for (int off = 16; off; off >>= 1) s += __shfl_xor_sync(0xffffffffu, s, off);
    if (lane == 0) red[warp] = s;
    __syncthreads();
    if (tid == 0) {
        float ss = 0.f;
        for (int i = 0; i < 8; i++) ss += red[i];
        stat[1] = ss;
    }
    __syncthreads();
    float inv = 1.0f / stat[1];

    float* attn = out + BB * DD + b * TT;
#pragma unroll
    for (int j = 0; j < 8; j++) attn[tid + j * 256] = vals[j] * inv;

    out[b * DD + tid] = 0.f;
    out[b * DD + 256 + tid] = 0.f;
}

// ---------------------------------------------------------------------------
// K3: context[b,d] = sum_t attn[b,t] * features[b,t,d]
// ---------------------------------------------------------------------------
__global__ void context_kernel(const float* __restrict__ features,
                               float* __restrict__ out) {
    int b = blockIdx.y;
    int t0 = blockIdx.x * 32;
    int j = threadIdx.x;  // d = 4j
    const float* fb = features + ((size_t)(b * TT + t0)) * DD + j * 4;
    const float* ap = out + BB * DD + b * TT + t0;

    float4 acc = make_float4(0.f, 0.f, 0.f, 0.f);
#pragma unroll 4
    for (int t = 0; t < 32; t++) {
        float w = ap[t];
        float4 f = *reinterpret_cast<const float4*>(fb + (size_t)t * DD);
        acc.x = fmaf(w, f.x, acc.x);
        acc.y = fmaf(w, f.y, acc.y);
        acc.z = fmaf(w, f.z, acc.z);
        acc.w = fmaf(w, f.w, acc.w);
    }
    float* cp = out + b * DD + j * 4;
    atomicAdd(cp + 0, acc.x);
    atomicAdd(cp + 1, acc.y);
    atomicAdd(cp + 2, acc.z);
    atomicAdd(cp + 3, acc.w);
}

// ---------------------------------------------------------------------------
extern "C" void kernel_launch(void* const* d_in, const int* in_sizes, int n_in,
                              void* d_out, int out_size) {
    const float* features = (const float*)d_in[0];
    const float* hidden   = (const float*)d_in[1];
    const float* W1       = (const float*)d_in[2];
    const float* b1       = (const float*)d_in[3];
    const float* W2       = (const float*)d_in[4];
    const float* b2       = (const float*)d_in[5];
    const float* V        = (const float*)d_in[6];
    const float* bv       = (const float*)d_in[7];
    float* out = (float*)d_out;

    cudaFuncSetAttribute(fused_score_kernel,
                         cudaFuncAttributeMaxDynamicSharedMemorySize, SMEM_BYTES);

    pack_w1<<<1024, 256>>>(W1);
    projh_kernel<<<BB, UU>>>(hidden, W2, b1, b2);
    fused_score_kernel<<<(BB * TT) / 128, 256, SMEM_BYTES>>>(features, V, bv);
    softmax_kernel<<<BB, 256>>>(out);
    context_kernel<<<dim3(TT / 32, BB), 128>>>(features, out);
}

// round 7
// speedup vs baseline: 1.7752x; 1.1169x over previous
#include <cuda_runtime.h>
#include <cuda_fp16.h>
#include <cstdint>

#define BB 32
#define TT 2048
#define DD 512
#define UU 512

// Scratch (no device allocation allowed)
__device__ float g_projh[BB * UU];       // hidden@W2 + b2 + b1 (b1 folded)
__device__ float g_logits[BB * TT];
__device__ __half g_w1p[UU * DD];        // W1 fragment-packed fp16 (rn)

// ---------------------------------------------------------------------------
// helpers
// ---------------------------------------------------------------------------
__device__ __forceinline__ uint32_t smem_u32(const void* p) {
    uint32_t a;
    asm("{ .reg .u64 t; cvta.to.shared.u64 t, %1; cvt.u32.u64 %0, t; }" : "=r"(a) : "l"(p));
    return a;
}
__device__ __forceinline__ float tanhap(float x) {
    float y;
    asm("tanh.approx.f32 %0, %1;" : "=f"(y) : "f"(x));
    return y;
}
__device__ __forceinline__ void cp16s(uint32_t s, const void* g) {
    asm volatile("cp.async.cg.shared.global [%0], [%1], 16;" :: "r"(s), "l"(g) : "memory");
}
#define CP_COMMIT() asm volatile("cp.async.commit_group;" ::: "memory")

__device__ __forceinline__ uint32_t packh2(float lo, float hi) {
    uint32_t r;
    asm("cvt.rn.f16x2.f32 %0, %1, %2;" : "=r"(r) : "f"(hi), "f"(lo));
    return r;
}
__device__ __forceinline__ void mma_f16(float* c, const uint32_t* a, uint32_t b0, uint32_t b1) {
    asm volatile(
        "mma.sync.aligned.m16n8k16.row.col.f32.f16.f16.f32 "
        "{%0,%1,%2,%3}, {%4,%5,%6,%7}, {%8,%9}, {%0,%1,%2,%3};"
        : "+f"(c[0]), "+f"(c[1]), "+f"(c[2]), "+f"(c[3])
        : "r"(a[0]), "r"(a[1]), "r"(a[2]), "r"(a[3]), "r"(b0), "r"(b1));
}

// ---------------------------------------------------------------------------
// P0: pack W1 [D,U] -> g_w1p (fp16, m16n8k16 B-fragment order).
// tile = (nsub=u>>7)*8 + (kc6=d>>6); within tile (8192 halves):
//   ks=(d>>4)&3, r=d&15, tg=(r&7)>>1, hidx=(r>>3)*2+(r&1), un=u&127
//   off = ((ks*128+un)*4 + tg)*4 + hidx
// ---------------------------------------------------------------------------
__global__ void pack_w1(const float* __restrict__ W1) {
    int idx = blockIdx.x * 256 + threadIdx.x;  // 0..262143
    int d = idx >> 9, u = idx & 511;
    __half v = __float2half_rn(W1[idx]);
    int kc6 = d >> 6, ks = (d >> 4) & 3, r = d & 15;
    int tg = (r & 7) >> 1, hidx = (r >> 3) * 2 + (r & 1);
    int nsub = u >> 7, un = u & 127;
    g_w1p[(size_t)(nsub * 8 + kc6) * 8192 + ((ks * 128 + un) * 4 + tg) * 4 + hidx] = v;
}

// ---------------------------------------------------------------------------
// P1: g_projh[b,u] = hidden[b,:] . W2[:,u] + b2[u] + b1[u]
// ---------------------------------------------------------------------------
__global__ void projh_kernel(const float* __restrict__ hidden,
                             const float* __restrict__ W2,
                             const float* __restrict__ b1,
                             const float* __restrict__ b2) {
    __shared__ float hs[DD];
    int b = blockIdx.x, u = threadIdx.x;
    hs[u] = hidden[b * DD + u];
    __syncthreads();
    float acc = b1[u] + b2[u];
#pragma unroll 16
    for (int d = 0; d < DD; d++) acc = fmaf(hs[d], W2[d * UU + u], acc);
    g_projh[b * UU + u] = acc;
}

// ---------------------------------------------------------------------------
// K1: fused GEMM 128x512x512 (fp16 MMA, fp32 accum) + tanh + V-contract.
// 16 chunks of K=64 (c = nc*8 + kc); single barrier per chunk; 2-stage B;
// A converted fp32->fp16 fragments in-loop (chunk c converts c+1, nc=0 only),
// LDG latency hidden under the tensor-pipe drain of the just-issued MMAs.
// smem: packA[128KB] | B[2][32KB] | projh | V | logit
// ---------------------------------------------------------------------------
#define PACKA_OFF 0                    // 131072 B (8 chunks * 16KB)
#define B_OFF 131072
#define B_STAGE_B 32768
#define PROJ_OFF 196608
#define V_OFF 198656
#define LOG_OFF 200704
#define SMEM_BYTES 201216

__device__ __forceinline__ void load_b(uint32_t sb, int c, int tid) {
    uint32_t bbase = sb + B_OFF + (c & 1) * B_STAGE_B;
    const int nc = c >> 3, kc6 = c & 7;
#pragma unroll
    for (int sub = 0; sub < 2; sub++) {
        const __half* Bg = g_w1p + (size_t)((nc * 2 + sub) * 8 + kc6) * 8192;
#pragma unroll
        for (int j = 0; j < 4; j++) {
            int q = tid + j * 256;     // 1024 16B units per subtile
            cp16s(bbase + sub * 16384 + q * 16, Bg + q * 8);
        }
    }
    CP_COMMIT();
}

__device__ __forceinline__ void convertA(char* smem, const float* __restrict__ features,
                                         int m0, int kc, int tid) {
    uint4* pk = (uint4*)(smem + PACKA_OFF) + kc * 1024;
#pragma unroll
    for (int j = 0; j < 4; j++) {
        int q = tid + j * 256;          // 1024 fragment-quads per chunk
        int ln = q & 31, rest = q >> 5;
        int mt8 = rest >> 2, ks = rest & 3;
        int gq = ln >> 2, tq = ln & 3;
        int mA = mt8 * 16 + gq;
        int k0 = kc * 64 + ks * 16 + 2 * tq;
        const float* fA = features + (size_t)(m0 + mA) * DD + k0;
        const float* fB = fA + 8 * DD;  // row mA+8
        float2 xA0 = __ldg((const float2*)fA);
        float2 xB0 = __ldg((const float2*)fB);
        float2 xA1 = __ldg((const float2*)(fA + 8));
        float2 xB1 = __ldg((const float2*)(fB + 8));
        uint4 v;
        v.x = packh2(xA0.x, xA0.y);
        v.y = packh2(xB0.x, xB0.y);
        v.z = packh2(xA1.x, xA1.y);
        v.w = packh2(xB1.x, xB1.y);
        pk[q] = v;
    }
}

__global__ void __launch_bounds__(256, 1)
fused_score_kernel(const float* __restrict__ features,
                   const float* __restrict__ V,
                   const float* __restrict__ bv) {
    extern __shared__ __align__(128) char smem[];
    const uint32_t sb = smem_u32(smem);
    const int tid = threadIdx.x;
    const int warp = tid >> 5, lane = tid & 31;
    const int g = lane >> 2, tg = lane & 3;
    const int wm = warp >> 2, wn = warp & 3;       // 2 x 4
    const int mbase = wm * 64, nbase = wn * 64;
    const int m0 = blockIdx.x * 128;
    const int bb = m0 >> 11;

    float* projh_s = (float*)(smem + PROJ_OFF);
    float* Vs = (float*)(smem + V_OFF);
    float* logit_s = (float*)(smem + LOG_OFF);
    const float bv0 = bv[0];

    // prologue: B(0) in flight, convert A chunk 0, load per-CTA vectors
    load_b(sb, 0, tid);
    convertA(smem, features, m0, 0, tid);
    for (int i = tid; i < 512; i += 256) {
        projh_s[i] = g_projh[bb * UU + i];
        Vs[i] = V[i];
    }
    if (tid < 128) logit_s[tid] = 0.f;

    const uint4* pkA = (const uint4*)(smem + PACKA_OFF);
    float c[4][8][4];

    for (int cc = 0; cc < 16; cc++) {
        const int s = cc & 1;
        const int kcA = cc & 7;
        if (kcA == 0) {
#pragma unroll
            for (int i = 0; i < 4; i++)
#pragma unroll
                for (int j = 0; j < 8; j++)
#pragma unroll
                    for (int k = 0; k < 4; k++) c[i][j][k] = 0.f;
        }

        asm volatile("cp.async.wait_group 0;" ::: "memory");
        __syncthreads();   // single barrier per chunk
        if (cc + 1 < 16) load_b(sb, cc + 1, tid);

        // MMA: warp tile 64x64, 128 m16n8k16 per warp per chunk
        const char* Bs = smem + B_OFF + s * B_STAGE_B + (wn >> 1) * 16384;
        const int nloc0 = (wn & 1) * 64;
#pragma unroll
        for (int ks = 0; ks < 4; ks++) {
            uint32_t a[4][4];
#pragma unroll
            for (int mt = 0; mt < 4; mt++) {
                uint4 v = pkA[kcA * 1024 + ((wm * 4 + mt) * 4 + ks) * 32 + lane];
                a[mt][0] = v.x; a[mt][1] = v.y; a[mt][2] = v.z; a[mt][3] = v.w;
            }
            uint32_t b[8][2];
#pragma unroll
            for (int nt = 0; nt < 8; nt++) {
                int nl = nloc0 + nt * 8 + g;
                uint2 bp = *(const uint2*)(Bs + ((ks * 128 + nl) * 4 + tg) * 8);
                b[nt][0] = bp.x; b[nt][1] = bp.y;
            }
#pragma unroll
            for (int mt = 0; mt < 4; mt++)
#pragma unroll
                for (int nt = 0; nt < 8; nt++)
                    mma_f16(c[mt][nt], a[mt], b[nt][0], b[nt][1]);
        }

        // convert next A chunk while the tensor pipe drains (nc=0 pass only)
        if (cc + 1 < 8) convertA(smem, features, m0, cc + 1, tid);

        if (kcA == 7) {
            const int nc = cc >> 3;
            // epilogue: tanh(+projh) . V
#pragma unroll
            for (int mt = 0; mt < 4; mt++) {
                float p0 = 0.f, p1 = 0.f;
#pragma unroll
                for (int nt = 0; nt < 8; nt++) {
                    int u0 = nc * 256 + nbase + nt * 8 + 2 * tg;
                    float ph0 = projh_s[u0], ph1 = projh_s[u0 + 1];
                    float v0 = Vs[u0], v1 = Vs[u0 + 1];
                    p0 += tanhap(c[mt][nt][0] + ph0) * v0;
                    p0 += tanhap(c[mt][nt][1] + ph1) * v1;
                    p1 += tanhap(c[mt][nt][2] + ph0) * v0;
                    p1 += tanhap(c[mt][nt][3] + ph1) * v1;
                }
                p0 += __shfl_xor_sync(0xffffffffu, p0, 1);
                p0 += __shfl_xor_sync(0xffffffffu, p0, 2);
                p1 += __shfl_xor_sync(0xffffffffu, p1, 1);
                p1 += __shfl_xor_sync(0xffffffffu, p1, 2);
                if (tg == 0) {
                    atomicAdd(&logit_s[mbase + mt * 16 + g], p0);
                    atomicAdd(&logit_s[mbase + mt * 16 + 8 + g], p1);
                }
            }
        }
    }
    __syncthreads();
    if (tid < 128) g_logits[m0 + tid] = logit_s[tid] + bv0;
}

// ---------------------------------------------------------------------------
// K2: softmax over T per batch; writes attn; zeroes context region.
// ---------------------------------------------------------------------------
__global__ void softmax_kernel(float* __restrict__ out) {
    int b = blockIdx.x;
    int tid = threadIdx.x;  // 256
    const float* lg = g_logits + b * TT;

    float vals[8];
    float m = -3.4e38f;
#pragma unroll
    for (int j = 0; j < 8; j++) {
        vals[j] = lg[tid + j * 256];
        m = fmaxf(m, vals[j]);
    }
#pragma unroll
    for (int off = 16; off; off >>= 1) m = fmaxf(m, __shfl_xor_sync(0xffffffffu, m, off));

    __shared__ float red[8];
    __shared__ float stat[2];
    int warp = tid >> 5, lane = tid & 31;
    if (lane == 0) red[warp] = m;
    __syncthreads();
    if (tid == 0) {
        float mm = red[0];
        for (int i = 1; i < 8; i++) mm = fmaxf(mm, red[i]);
        stat[0] = mm;
    }
    __syncthreads();
    float smax = stat[0];

    float s = 0.f;
#pragma unroll
    for (int j = 0; j < 8; j++) {
        vals[j] = __expf(vals[j] - smax);
        s += vals[j];
    }
#pragma unroll
    for (int off = 16; off; off >>= 1) s += __shfl_xor_sync(0xffffffffu, s, off);
    if (lane == 0) red[warp] = s;
    __syncthreads();
    if (tid == 0) {
        float ss = 0.f;
        for (int i = 0; i < 8; i++) ss += red[i];
        stat[1] = ss;
    }
    __syncthreads();
    float inv = 1.0f / stat[1];

    float* attn = out + BB * DD + b * TT;
#pragma unroll
    for (int j = 0; j < 8; j++) attn[tid + j * 256] = vals[j] * inv;

    out[b * DD + tid] = 0.f;
    out[b * DD + 256 + tid] = 0.f;
}

// ---------------------------------------------------------------------------
// K3: context[b,d] = sum_t attn[b,t] * features[b,t,d]
// ---------------------------------------------------------------------------
__global__ void context_kernel(const float* __restrict__ features,
                               float* __restrict__ out) {
    int b = blockIdx.y;
    int t0 = blockIdx.x * 32;
    int j = threadIdx.x;  // d = 4j
    const float* fb = features + ((size_t)(b * TT + t0)) * DD + j * 4;
    const float* ap = out + BB * DD + b * TT + t0;

    float4 acc = make_float4(0.f, 0.f, 0.f, 0.f);
#pragma unroll 4
    for (int t = 0; t < 32; t++) {
        float w = ap[t];
        float4 f = *reinterpret_cast<const float4*>(fb + (size_t)t * DD);
        acc.x = fmaf(w, f.x, acc.x);
        acc.y = fmaf(w, f.y, acc.y);
        acc.z = fmaf(w, f.z, acc.z);
        acc.w = fmaf(w, f.w, acc.w);
    }
    float* cp = out + b * DD + j * 4;
    atomicAdd(cp + 0, acc.x);
    atomicAdd(cp + 1, acc.y);
    atomicAdd(cp + 2, acc.z);
    atomicAdd(cp + 3, acc.w);
}

// ---------------------------------------------------------------------------
extern "C" void kernel_launch(void* const* d_in, const int* in_sizes, int n_in,
                              void* d_out, int out_size) {
    const float* features = (const float*)d_in[0];
    const float* hidden   = (const float*)d_in[1];
    const float* W1       = (const float*)d_in[2];
    const float* b1       = (const float*)d_in[3];
    const float* W2       = (const float*)d_in[4];
    const float* b2       = (const float*)d_in[5];
    const float* V        = (const float*)d_in[6];
    const float* bv       = (const float*)d_in[7];
    float* out = (float*)d_out;

    cudaFuncSetAttribute(fused_score_kernel,
                         cudaFuncAttributeMaxDynamicSharedMemorySize, SMEM_BYTES);

    pack_w1<<<1024, 256>>>(W1);
    projh_kernel<<<BB, UU>>>(hidden, W2, b1, b2);
    fused_score_kernel<<<(BB * TT) / 128, 256, SMEM_BYTES>>>(features, V, bv);
    softmax_kernel<<<BB, 256>>>(out);
    context_kernel<<<dim3(TT / 32, BB), 128>>>(features, out);
}